// round 9
// baseline (speedup 1.0000x reference)
#include <cuda_runtime.h>
#include <cuda_bf16.h>
#include <cstdint>

// Problem constants
#define BATCH 4
#define SEQ   2048
#define DM    1024
#define NH    16
#define HD    64
#define M_ROWS (BATCH*SEQ)   // 8192

// Scratch (device globals; no allocation allowed)
__device__ float g_qkv[(size_t)M_ROWS * 3 * DM];   // [B*T, 3*C] (sel, head, hd)
__device__ float g_y[(size_t)M_ROWS * DM];         // [B*T, C]

__device__ __forceinline__ uint32_t f2tf(float f) {
    uint32_t u;
    asm("cvt.rna.tf32.f32 %0, %1;" : "=r"(u) : "f"(f));
    return u;
}

#define MMA_TF32(acc, a, b0v, b1v)                                              \
    asm volatile(                                                               \
        "mma.sync.aligned.m16n8k8.row.col.f32.tf32.tf32.f32 "                   \
        "{%0,%1,%2,%3}, {%4,%5,%6,%7}, {%8,%9}, {%0,%1,%2,%3};"                 \
        : "+f"(acc[0]), "+f"(acc[1]), "+f"(acc[2]), "+f"(acc[3])                \
        : "r"(a[0]), "r"(a[1]), "r"(a[2]), "r"(a[3]), "r"(b0v), "r"(b1v))

#define TFS 136   // B smem row stride (= 8 mod 32 -> conflict-free quad loads)
#define AS2 264   // A smem row stride for 256-tile kernel (= 8 mod 32)

// ---------------------------------------------------------------------------
// Kernel 1 (proven round-7): 128x128 tile, BK=16, 256 thr (8 warps 4x2),
// warp tile 32x64. tf32 stored in smem (cvt at store). Used for proj.
// ---------------------------------------------------------------------------
__global__ __launch_bounds__(256) void tf32_gemm_bias(
    const float* __restrict__ A, const float* __restrict__ B,
    const float* __restrict__ bias, float* __restrict__ C,
    int M, int N, int K)
{
    __shared__ uint32_t As[2][16][TFS];
    __shared__ uint32_t Bs[2][16][TFS];

    const int tid  = threadIdx.x;
    const int lane = tid & 31;
    const int wid  = tid >> 5;
    const int gid  = lane >> 2;
    const int tig  = lane & 3;
    const int wm   = (wid & 3) * 32;
    const int wn   = (wid >> 2) * 64;
    const int bm   = blockIdx.y * 128;
    const int bn   = blockIdx.x * 128;

    const int ar = tid >> 2;
    const int ac = (tid & 3) * 4;
    const int br = tid >> 4;
    const int bc = (tid & 15) * 4;

    const float* Ap = A + (size_t)(bm + ar) * K + ac;
    const float* Bp = B + (size_t)br * N + bn + bc;

    float acc[2][8][4];
#pragma unroll
    for (int mt = 0; mt < 2; mt++)
#pragma unroll
        for (int nt = 0; nt < 8; nt++)
#pragma unroll
            for (int i = 0; i < 4; i++) acc[mt][nt][i] = 0.f;

    const int ntiles = K / 16;
    float4 pa0, pa1, pb0, pb1;

    {
        pa0 = *(const float4*)(Ap);
        pa1 = *(const float4*)(Ap + (size_t)64 * K);
        pb0 = *(const float4*)(Bp);
        pb1 = *(const float4*)(Bp + 64);
        As[0][ac + 0][ar]      = f2tf(pa0.x);
        As[0][ac + 1][ar]      = f2tf(pa0.y);
        As[0][ac + 2][ar]      = f2tf(pa0.z);
        As[0][ac + 3][ar]      = f2tf(pa0.w);
        As[0][ac + 0][ar + 64] = f2tf(pa1.x);
        As[0][ac + 1][ar + 64] = f2tf(pa1.y);
        As[0][ac + 2][ar + 64] = f2tf(pa1.z);
        As[0][ac + 3][ar + 64] = f2tf(pa1.w);
        Bs[0][br][bc + 0]      = f2tf(pb0.x);
        Bs[0][br][bc + 1]      = f2tf(pb0.y);
        Bs[0][br][bc + 2]      = f2tf(pb0.z);
        Bs[0][br][bc + 3]      = f2tf(pb0.w);
        Bs[0][br][bc + 64]     = f2tf(pb1.x);
        Bs[0][br][bc + 65]     = f2tf(pb1.y);
        Bs[0][br][bc + 66]     = f2tf(pb1.z);
        Bs[0][br][bc + 67]     = f2tf(pb1.w);
    }
    __syncthreads();

    int buf = 0;
    for (int t = 0; t < ntiles; t++) {
        if (t + 1 < ntiles) {
            const int k0 = (t + 1) * 16;
            pa0 = *(const float4*)(Ap + k0);
            pa1 = *(const float4*)(Ap + (size_t)64 * K + k0);
            pb0 = *(const float4*)(Bp + (size_t)k0 * N);
            pb1 = *(const float4*)(Bp + (size_t)k0 * N + 64);
        }

#pragma unroll
        for (int kk = 0; kk < 16; kk += 8) {
            uint32_t af[2][4], bf[8][2];
#pragma unroll
            for (int mt = 0; mt < 2; mt++) {
                const int r = wm + mt * 16 + gid;
                af[mt][0] = As[buf][kk + tig][r];
                af[mt][1] = As[buf][kk + tig][r + 8];
                af[mt][2] = As[buf][kk + tig + 4][r];
                af[mt][3] = As[buf][kk + tig + 4][r + 8];
            }
#pragma unroll
            for (int nt = 0; nt < 8; nt++) {
                const int c = wn + nt * 8 + gid;
                bf[nt][0] = Bs[buf][kk + tig][c];
                bf[nt][1] = Bs[buf][kk + tig + 4][c];
            }
#pragma unroll
            for (int mt = 0; mt < 2; mt++)
#pragma unroll
                for (int nt = 0; nt < 8; nt++)
                    MMA_TF32(acc[mt][nt], af[mt], bf[nt][0], bf[nt][1]);
        }

        if (t + 1 < ntiles) {
            const int nb = buf ^ 1;
            As[nb][ac + 0][ar]      = f2tf(pa0.x);
            As[nb][ac + 1][ar]      = f2tf(pa0.y);
            As[nb][ac + 2][ar]      = f2tf(pa0.z);
            As[nb][ac + 3][ar]      = f2tf(pa0.w);
            As[nb][ac + 0][ar + 64] = f2tf(pa1.x);
            As[nb][ac + 1][ar + 64] = f2tf(pa1.y);
            As[nb][ac + 2][ar + 64] = f2tf(pa1.z);
            As[nb][ac + 3][ar + 64] = f2tf(pa1.w);
            Bs[nb][br][bc + 0]      = f2tf(pb0.x);
            Bs[nb][br][bc + 1]      = f2tf(pb0.y);
            Bs[nb][br][bc + 2]      = f2tf(pb0.z);
            Bs[nb][br][bc + 3]      = f2tf(pb0.w);
            Bs[nb][br][bc + 64]     = f2tf(pb1.x);
            Bs[nb][br][bc + 65]     = f2tf(pb1.y);
            Bs[nb][br][bc + 66]     = f2tf(pb1.z);
            Bs[nb][br][bc + 67]     = f2tf(pb1.w);
        }
        __syncthreads();
        buf ^= 1;
    }

#pragma unroll
    for (int mt = 0; mt < 2; mt++) {
        const int r0 = bm + wm + mt * 16 + gid;
#pragma unroll
        for (int nt = 0; nt < 8; nt++) {
            const int col = bn + wn + nt * 8 + 2 * tig;
            const float bx = bias[col], by = bias[col + 1];
            float2 v0 = {acc[mt][nt][0] + bx, acc[mt][nt][1] + by};
            float2 v1 = {acc[mt][nt][2] + bx, acc[mt][nt][3] + by};
            *(float2*)(C + (size_t)r0 * N + col)       = v0;
            *(float2*)(C + (size_t)(r0 + 8) * N + col) = v1;
        }
    }
}

// ---------------------------------------------------------------------------
// Kernel 2 (experiment, used for qkv): 256x128 tile, BK=16, 256 thr,
// 8 warps 4x2, warp tile 64x64 -> 4B fragment LDS per mma (-33%).
// A smem [k][row] stride 264, B smem [k][col] stride 136; cvt at store.
// M % 256 == 0 required.
// ---------------------------------------------------------------------------
__global__ __launch_bounds__(256) void tf32_gemm_bias_256(
    const float* __restrict__ A, const float* __restrict__ B,
    const float* __restrict__ bias, float* __restrict__ C,
    int M, int N, int K)
{
    __shared__ uint32_t As[2][16][AS2];   // [k][row 0..255]
    __shared__ uint32_t Bs[2][16][TFS];   // [k][col 0..127]

    const int tid  = threadIdx.x;
    const int lane = tid & 31;
    const int wid  = tid >> 5;
    const int gid  = lane >> 2;
    const int tig  = lane & 3;
    const int wm   = (wid & 3) * 64;
    const int wn   = (wid >> 2) * 64;
    const int bm   = blockIdx.y * 256;
    const int bn   = blockIdx.x * 128;

    // A: thread loads row tid, 16 k values. B: 8 cols x 1 k-row per thread.
    const int brow = tid >> 4;
    const int bc8  = (tid & 15) * 8;

    const float* Ap = A + (size_t)(bm + tid) * K;
    const float* Bp = B + (size_t)brow * N + bn + bc8;

    float acc[4][8][4];
#pragma unroll
    for (int mt = 0; mt < 4; mt++)
#pragma unroll
        for (int nt = 0; nt < 8; nt++)
#pragma unroll
            for (int i = 0; i < 4; i++) acc[mt][nt][i] = 0.f;

    const int ntiles = K / 16;
    float4 pa[4], pb[2];

    // Preload tile 0 -> buf 0
    {
#pragma unroll
        for (int j = 0; j < 4; j++) pa[j] = ((const float4*)Ap)[j];
        pb[0] = *(const float4*)(Bp);
        pb[1] = *(const float4*)(Bp + 4);
#pragma unroll
        for (int j = 0; j < 4; j++) {
            As[0][4*j + 0][tid] = f2tf(pa[j].x);
            As[0][4*j + 1][tid] = f2tf(pa[j].y);
            As[0][4*j + 2][tid] = f2tf(pa[j].z);
            As[0][4*j + 3][tid] = f2tf(pa[j].w);
        }
        Bs[0][brow][bc8 + 0] = f2tf(pb[0].x);
        Bs[0][brow][bc8 + 1] = f2tf(pb[0].y);
        Bs[0][brow][bc8 + 2] = f2tf(pb[0].z);
        Bs[0][brow][bc8 + 3] = f2tf(pb[0].w);
        Bs[0][brow][bc8 + 4] = f2tf(pb[1].x);
        Bs[0][brow][bc8 + 5] = f2tf(pb[1].y);
        Bs[0][brow][bc8 + 6] = f2tf(pb[1].z);
        Bs[0][brow][bc8 + 7] = f2tf(pb[1].w);
    }
    __syncthreads();

    int buf = 0;
    for (int t = 0; t < ntiles; t++) {
        if (t + 1 < ntiles) {
            const int k0 = (t + 1) * 16;
            const float* ap = Ap + k0;
            const float* bp = Bp + (size_t)k0 * N;
#pragma unroll
            for (int j = 0; j < 4; j++) pa[j] = ((const float4*)ap)[j];
            pb[0] = *(const float4*)(bp);
            pb[1] = *(const float4*)(bp + 4);
        }

#pragma unroll
        for (int kk = 0; kk < 16; kk += 8) {
            uint32_t af[4][4], bf[8][2];
#pragma unroll
            for (int mt = 0; mt < 4; mt++) {
                const int r = wm + mt * 16 + gid;
                af[mt][0] = As[buf][kk + tig][r];
                af[mt][1] = As[buf][kk + tig][r + 8];
                af[mt][2] = As[buf][kk + tig + 4][r];
                af[mt][3] = As[buf][kk + tig + 4][r + 8];
            }
#pragma unroll
            for (int nt = 0; nt < 8; nt++) {
                const int c = wn + nt * 8 + gid;
                bf[nt][0] = Bs[buf][kk + tig][c];
                bf[nt][1] = Bs[buf][kk + tig + 4][c];
            }
#pragma unroll
            for (int mt = 0; mt < 4; mt++)
#pragma unroll
                for (int nt = 0; nt < 8; nt++)
                    MMA_TF32(acc[mt][nt], af[mt], bf[nt][0], bf[nt][1]);
        }

        if (t + 1 < ntiles) {
            const int nb = buf ^ 1;
#pragma unroll
            for (int j = 0; j < 4; j++) {
                As[nb][4*j + 0][tid] = f2tf(pa[j].x);
                As[nb][4*j + 1][tid] = f2tf(pa[j].y);
                As[nb][4*j + 2][tid] = f2tf(pa[j].z);
                As[nb][4*j + 3][tid] = f2tf(pa[j].w);
            }
            Bs[nb][brow][bc8 + 0] = f2tf(pb[0].x);
            Bs[nb][brow][bc8 + 1] = f2tf(pb[0].y);
            Bs[nb][brow][bc8 + 2] = f2tf(pb[0].z);
            Bs[nb][brow][bc8 + 3] = f2tf(pb[0].w);
            Bs[nb][brow][bc8 + 4] = f2tf(pb[1].x);
            Bs[nb][brow][bc8 + 5] = f2tf(pb[1].y);
            Bs[nb][brow][bc8 + 6] = f2tf(pb[1].z);
            Bs[nb][brow][bc8 + 7] = f2tf(pb[1].w);
        }
        __syncthreads();
        buf ^= 1;
    }

    // Epilogue with bias
#pragma unroll
    for (int mt = 0; mt < 4; mt++) {
        const int r0 = bm + wm + mt * 16 + gid;
#pragma unroll
        for (int nt = 0; nt < 8; nt++) {
            const int col = bn + wn + nt * 8 + 2 * tig;
            const float bx = bias[col], by = bias[col + 1];
            float2 v0 = {acc[mt][nt][0] + bx, acc[mt][nt][1] + by};
            float2 v1 = {acc[mt][nt][2] + bx, acc[mt][nt][3] + by};
            *(float2*)(C + (size_t)r0 * N + col)       = v0;
            *(float2*)(C + (size_t)(r0 + 8) * N + col) = v1;
        }
    }
}

// ---------------------------------------------------------------------------
// Tensor-core flash attention (round-8 version, measured faster):
// 128 queries/block, 4 warps x 32 queries, P in registers via quad shfl.
// ---------------------------------------------------------------------------
__global__ __launch_bounds__(128) void flash_attn_tc(
    const float* __restrict__ qkv, float* __restrict__ y)
{
    __shared__ uint32_t ks[64][68];
    __shared__ uint32_t vst[64][68];

    const int tid  = threadIdx.x;
    const int lane = tid & 31;
    const int wid  = tid >> 5;
    const int gid  = lane >> 2;
    const int tig  = lane & 3;
    const int wq   = wid * 32;
    const int qt0  = (int)(gridDim.x - 1 - blockIdx.x) * 128;
    const int h    = blockIdx.y;
    const int b    = blockIdx.z;

    uint32_t qf[2][8][4];
#pragma unroll
    for (int mt = 0; mt < 2; mt++) {
        const float* q0 = qkv + ((size_t)(b * SEQ + qt0 + wq + mt * 16 + gid) * (3 * DM)) + h * HD;
        const float* q1 = q0 + (size_t)8 * 3 * DM;
#pragma unroll
        for (int kk = 0; kk < 8; kk++) {
            qf[mt][kk][0] = f2tf(q0[kk * 8 + tig]     * 0.125f);
            qf[mt][kk][1] = f2tf(q1[kk * 8 + tig]     * 0.125f);
            qf[mt][kk][2] = f2tf(q0[kk * 8 + tig + 4] * 0.125f);
            qf[mt][kk][3] = f2tf(q1[kk * 8 + tig + 4] * 0.125f);
        }
    }

    float o[2][8][4];
#pragma unroll
    for (int mt = 0; mt < 2; mt++)
#pragma unroll
        for (int nt = 0; nt < 8; nt++) {
            o[mt][nt][0] = 0.f; o[mt][nt][1] = 0.f;
            o[mt][nt][2] = 0.f; o[mt][nt][3] = 0.f;
        }
    float m[2][2] = {{-1e30f, -1e30f}, {-1e30f, -1e30f}};
    float l[2][2] = {{0.f, 0.f}, {0.f, 0.f}};

    const int ntiles = qt0 / 64 + 2;
    const int krow = tid & 63;
    const int kcb  = (tid >> 6) * 32;

    const int src0 = tig >> 1;
    const int src2 = (tig >> 1) + 2;
    const bool sel = (tig & 1);

    for (int kt = 0; kt < ntiles; kt++) {
        const int kt0 = kt * 64;

        __syncthreads();
        {
            const float* kp = qkv + ((size_t)(b * SEQ + kt0 + krow) * (3 * DM)) + DM + h * HD + kcb;
            const float* vp = kp + DM;
#pragma unroll
            for (int j = 0; j < 32; j += 4) {
                float4 k4 = *(const float4*)(kp + j);
                float4 v4 = *(const float4*)(vp + j);
                uint4 w;
                w.x = f2tf(k4.x); w.y = f2tf(k4.y); w.z = f2tf(k4.z); w.w = f2tf(k4.w);
                *(uint4*)&ks[krow][kcb + j] = w;
                vst[kcb + j + 0][krow] = f2tf(v4.x);
                vst[kcb + j + 1][krow] = f2tf(v4.y);
                vst[kcb + j + 2][krow] = f2tf(v4.z);
                vst[kcb + j + 3][krow] = f2tf(v4.w);
            }
        }
        __syncthreads();

        if (kt0 > qt0 + wq + 31) continue;

        float acc[2][8][4];
#pragma unroll
        for (int mt = 0; mt < 2; mt++)
#pragma unroll
            for (int nt = 0; nt < 8; nt++) {
                acc[mt][nt][0] = 0.f; acc[mt][nt][1] = 0.f;
                acc[mt][nt][2] = 0.f; acc[mt][nt][3] = 0.f;
            }
#pragma unroll
        for (int kk = 0; kk < 8; kk++) {
            uint32_t bf0[8], bf1[8];
#pragma unroll
            for (int nt = 0; nt < 8; nt++) {
                bf0[nt] = ks[nt * 8 + gid][kk * 8 + tig];
                bf1[nt] = ks[nt * 8 + gid][kk * 8 + tig + 4];
            }
#pragma unroll
            for (int mt = 0; mt < 2; mt++)
#pragma unroll
                for (int nt = 0; nt < 8; nt++)
                    MMA_TF32(acc[mt][nt], qf[mt][kk], bf0[nt], bf1[nt]);
        }

#pragma unroll
        for (int mt = 0; mt < 2; mt++) {
            if (kt0 + 63 > qt0 + wq + mt * 16) {
                const int r0 = qt0 + wq + mt * 16 + gid, r1 = r0 + 8;
#pragma unroll
                for (int nt = 0; nt < 8; nt++) {
                    const int c = kt0 + nt * 8 + 2 * tig;
                    if (c     > r0) acc[mt][nt][0] = -1e30f;
                    if (c + 1 > r0) acc[mt][nt][1] = -1e30f;
                    if (c     > r1) acc[mt][nt][2] = -1e30f;
                    if (c + 1 > r1) acc[mt][nt][3] = -1e30f;
                }
            }
        }

#pragma unroll
        for (int mt = 0; mt < 2; mt++) {
            float mt0 = -1e30f, mt1 = -1e30f;
#pragma unroll
            for (int nt = 0; nt < 8; nt++) {
                mt0 = fmaxf(mt0, fmaxf(acc[mt][nt][0], acc[mt][nt][1]));
                mt1 = fmaxf(mt1, fmaxf(acc[mt][nt][2], acc[mt][nt][3]));
            }
            mt0 = fmaxf(mt0, __shfl_xor_sync(0xffffffffu, mt0, 1));
            mt0 = fmaxf(mt0, __shfl_xor_sync(0xffffffffu, mt0, 2));
            mt1 = fmaxf(mt1, __shfl_xor_sync(0xffffffffu, mt1, 1));
            mt1 = fmaxf(mt1, __shfl_xor_sync(0xffffffffu, mt1, 2));

            const float mn0 = fmaxf(m[mt][0], mt0), mn1 = fmaxf(m[mt][1], mt1);
            const float cr0 = __expf(m[mt][0] - mn0), cr1 = __expf(m[mt][1] - mn1);
            m[mt][0] = mn0; m[mt][1] = mn1;
            l[mt][0] *= cr0; l[mt][1] *= cr1;

            float s0 = 0.f, s1 = 0.f;
#pragma unroll
            for (int nt = 0; nt < 8; nt++) {
                const float p0 = __expf(acc[mt][nt][0] - mn0);
                const float p1 = __expf(acc[mt][nt][1] - mn0);
                const float p2 = __expf(acc[mt][nt][2] - mn1);
                const float p3 = __expf(acc[mt][nt][3] - mn1);
                s0 += p0 + p1;
                s1 += p2 + p3;
                o[mt][nt][0] *= cr0; o[mt][nt][1] *= cr0;
                o[mt][nt][2] *= cr1; o[mt][nt][3] *= cr1;
                acc[mt][nt][0] = __uint_as_float(f2tf(p0));
                acc[mt][nt][1] = __uint_as_float(f2tf(p1));
                acc[mt][nt][2] = __uint_as_float(f2tf(p2));
                acc[mt][nt][3] = __uint_as_float(f2tf(p3));
            }
            s0 += __shfl_xor_sync(0xffffffffu, s0, 1);
            s0 += __shfl_xor_sync(0xffffffffu, s0, 2);
            s1 += __shfl_xor_sync(0xffffffffu, s1, 1);
            s1 += __shfl_xor_sync(0xffffffffu, s1, 2);
            l[mt][0] += s0; l[mt][1] += s1;
        }

#pragma unroll
        for (int kk = 0; kk < 8; kk++) {
            uint32_t pa[2][4];
#pragma unroll
            for (int mt = 0; mt < 2; mt++) {
                const uint32_t e0 = __float_as_uint(acc[mt][kk][0]);
                const uint32_t e1 = __float_as_uint(acc[mt][kk][1]);
                const uint32_t e2 = __float_as_uint(acc[mt][kk][2]);
                const uint32_t e3 = __float_as_uint(acc[mt][kk][3]);
                const uint32_t u0 = __shfl_sync(0xffffffffu, e0, src0, 4);
                const uint32_t u1 = __shfl_sync(0xffffffffu, e1, src0, 4);
                pa[mt][0] = sel ? u1 : u0;
                const uint32_t v0 = __shfl_sync(0xffffffffu, e2, src0, 4);
                const uint32_t v1 = __shfl_sync(0xffffffffu, e3, src0, 4);
                pa[mt][1] = sel ? v1 : v0;
                const uint32_t w0 = __shfl_sync(0xffffffffu, e0, src2, 4);
                const uint32_t w1 = __shfl_sync(0xffffffffu, e1, src2, 4);
                pa[mt][2] = sel ? w1 : w0;
                const uint32_t x0 = __shfl_sync(0xffffffffu, e2, src2, 4);
                const uint32_t x1 = __shfl_sync(0xffffffffu, e3, src2, 4);
                pa[mt][3] = sel ? x1 : x0;
            }
#pragma unroll
            for (int nt = 0; nt < 8; nt++) {
                const uint32_t b0 = vst[nt * 8 + gid][kk * 8 + tig];
                const uint32_t b1 = vst[nt * 8 + gid][kk * 8 + tig + 4];
#pragma unroll
                for (int mt = 0; mt < 2; mt++)
                    MMA_TF32(o[mt][nt], pa[mt], b0, b1);
            }
        }
    }

#pragma unroll
    for (int mt = 0; mt < 2; mt++) {
        const float i0 = 1.f / l[mt][0], i1 = 1.f / l[mt][1];
        float* y0 = y + (size_t)(b * SEQ + qt0 + wq + mt * 16 + gid) * DM + h * HD;
        float* y1 = y0 + (size_t)8 * DM;
#pragma unroll
        for (int nt = 0; nt < 8; nt++) {
            const int c = nt * 8 + 2 * tig;
            float2 w0 = {o[mt][nt][0] * i0, o[mt][nt][1] * i0};
            float2 w1 = {o[mt][nt][2] * i1, o[mt][nt][3] * i1};
            *(float2*)(y0 + c) = w0;
            *(float2*)(y1 + c) = w1;
        }
    }
}

// ---------------------------------------------------------------------------
// Launch
// ---------------------------------------------------------------------------
extern "C" void kernel_launch(void* const* d_in, const int* in_sizes, int n_in,
                              void* d_out, int out_size)
{
    (void)in_sizes; (void)n_in; (void)out_size;
    const float* x      = (const float*)d_in[0];
    const float* w_qkv  = (const float*)d_in[1];
    const float* b_qkv  = (const float*)d_in[2];
    const float* w_proj = (const float*)d_in[3];
    const float* b_proj = (const float*)d_in[4];
    float* out = (float*)d_out;

    float* qkv = nullptr;
    float* y   = nullptr;
    cudaGetSymbolAddress((void**)&qkv, g_qkv);
    cudaGetSymbolAddress((void**)&y,   g_y);

    // 1) QKV projection (experiment: 256x128 tile, 64x64 warp tile)
    tf32_gemm_bias_256<<<dim3(3 * DM / 128, M_ROWS / 256), 256>>>(
        x, w_qkv, b_qkv, qkv, M_ROWS, 3 * DM, DM);

    // 2) Causal flash attention (128 queries per block, 4 warps)
    flash_attn_tc<<<dim3(SEQ / 128, NH, BATCH), 128>>>(qkv, y);

    // 3) Output projection (proven round-7 kernel)
    tf32_gemm_bias<<<dim3(DM / 128, M_ROWS / 128), 256>>>(
        y, w_proj, b_proj, out, M_ROWS, DM, DM);
}

// round 10
// speedup vs baseline: 1.2036x; 1.2036x over previous
#include <cuda_runtime.h>
#include <cuda_bf16.h>
#include <cstdint>

// Problem constants
#define BATCH 4
#define SEQ   2048
#define DM    1024
#define NH    16
#define HD    64
#define M_ROWS (BATCH*SEQ)   // 8192

// Scratch (device globals; no allocation allowed)
__device__ float g_qkv[(size_t)M_ROWS * 3 * DM];   // [B*T, 3*C] (sel, head, hd)
__device__ float g_y[(size_t)M_ROWS * DM];         // [B*T, C]

__device__ __forceinline__ uint32_t f2tf(float f) {
    uint32_t u;
    asm("cvt.rna.tf32.f32 %0, %1;" : "=r"(u) : "f"(f));
    return u;
}

__device__ __forceinline__ uint32_t smem_u32(const void* p) {
    uint32_t a;
    asm("{ .reg .u64 t; cvta.to.shared.u64 t, %1; cvt.u32.u64 %0, t; }"
        : "=r"(a) : "l"(p));
    return a;
}

#define MMA_TF32(acc, a, b0v, b1v)                                              \
    asm volatile(                                                               \
        "mma.sync.aligned.m16n8k8.row.col.f32.tf32.tf32.f32 "                   \
        "{%0,%1,%2,%3}, {%4,%5,%6,%7}, {%8,%9}, {%0,%1,%2,%3};"                 \
        : "+f"(acc[0]), "+f"(acc[1]), "+f"(acc[2]), "+f"(acc[3])                \
        : "r"(a[0]), "r"(a[1]), "r"(a[2]), "r"(a[3]), "r"(b0v), "r"(b1v))

#define LDSM_X4(r, addr)                                                        \
    asm volatile(                                                               \
        "ldmatrix.sync.aligned.m8n8.x4.shared.b16 {%0,%1,%2,%3}, [%4];"         \
        : "=r"((r)[0]), "=r"((r)[1]), "=r"((r)[2]), "=r"((r)[3])                \
        : "r"(addr))

#define TFS 136   // B smem row stride (= 8 mod 32 -> conflict-free quad loads)
#define AST 20    // A smem row stride (16B-aligned; 20r mod 32 distinct for 8 rows)

// ---------------------------------------------------------------------------
// TF32 GEMM with bias: C[M,N] = A[M,K] @ B[K,N] + bias[N]
// r7 geometry (128x128 tile, BK=16 double-buffered, 256 thr, 8 warps 4x2,
// warp tile 32x64) with A-fragments loaded via ldmatrix.x4:
//   A smem [row][k] stride 20, tf32 stored at STS (cvt off critical path).
//   B smem [k][col] stride 136, scalar fragment loads (proven conflict-free).
// ---------------------------------------------------------------------------
__global__ __launch_bounds__(256) void tf32_gemm_bias(
    const float* __restrict__ A, const float* __restrict__ B,
    const float* __restrict__ bias, float* __restrict__ C,
    int M, int N, int K)
{
    __shared__ uint32_t As[2][128][AST];   // [buf][row][k]  (10240 B per buf)
    __shared__ uint32_t Bs[2][16][TFS];    // [buf][k][col]

    const int tid  = threadIdx.x;
    const int lane = tid & 31;
    const int wid  = tid >> 5;
    const int gid  = lane >> 2;
    const int tig  = lane & 3;
    const int wm   = (wid & 3) * 32;
    const int wn   = (wid >> 2) * 64;
    const int bm   = blockIdx.y * 128;
    const int bn   = blockIdx.x * 128;

    // A global-load / store indexing: thread -> (row ar, k ac..ac+7)
    const int ar = tid >> 1;
    const int ac = (tid & 1) * 8;
    // B (r7 mapping)
    const int br = tid >> 4;
    const int bc = (tid & 15) * 4;

    const float* Ap = A + (size_t)(bm + ar) * K + ac;
    const float* Bp = B + (size_t)br * N + bn + bc;

    // Per-thread ldmatrix base address for A fragments:
    // row = wm + (lane & 15), kcol = (lane >> 4) * 4
    const uint32_t aLdsm = smem_u32(&As[0][0][0]) +
        (uint32_t)(((wm + (lane & 15)) * AST + ((lane >> 4) << 2)) * 4);

    float acc[2][8][4];
#pragma unroll
    for (int mt = 0; mt < 2; mt++)
#pragma unroll
        for (int nt = 0; nt < 8; nt++)
#pragma unroll
            for (int i = 0; i < 4; i++) acc[mt][nt][i] = 0.f;

    const int ntiles = K / 16;
    float4 pa0, pa1, pb0, pb1;

    // Preload tile 0 -> buf 0
    {
        pa0 = *(const float4*)(Ap);
        pa1 = *(const float4*)(Ap + 4);
        pb0 = *(const float4*)(Bp);
        pb1 = *(const float4*)(Bp + 64);
        uint4 w0, w1;
        w0.x = f2tf(pa0.x); w0.y = f2tf(pa0.y); w0.z = f2tf(pa0.z); w0.w = f2tf(pa0.w);
        w1.x = f2tf(pa1.x); w1.y = f2tf(pa1.y); w1.z = f2tf(pa1.z); w1.w = f2tf(pa1.w);
        *(uint4*)&As[0][ar][ac]     = w0;
        *(uint4*)&As[0][ar][ac + 4] = w1;
        Bs[0][br][bc + 0]  = f2tf(pb0.x);
        Bs[0][br][bc + 1]  = f2tf(pb0.y);
        Bs[0][br][bc + 2]  = f2tf(pb0.z);
        Bs[0][br][bc + 3]  = f2tf(pb0.w);
        Bs[0][br][bc + 64] = f2tf(pb1.x);
        Bs[0][br][bc + 65] = f2tf(pb1.y);
        Bs[0][br][bc + 66] = f2tf(pb1.z);
        Bs[0][br][bc + 67] = f2tf(pb1.w);
    }
    __syncthreads();

    int buf = 0;
    for (int t = 0; t < ntiles; t++) {
        if (t + 1 < ntiles) {
            const int k0 = (t + 1) * 16;
            pa0 = *(const float4*)(Ap + k0);
            pa1 = *(const float4*)(Ap + k0 + 4);
            pb0 = *(const float4*)(Bp + (size_t)k0 * N);
            pb1 = *(const float4*)(Bp + (size_t)k0 * N + 64);
        }

        const uint32_t aBufAddr = aLdsm + (uint32_t)(buf * 10240);
#pragma unroll
        for (int kk = 0; kk < 16; kk += 8) {
            uint32_t af[2][4], bf[8][2];
            // A: one ldmatrix.x4 per 16-row sub-tile
            LDSM_X4(af[0], aBufAddr + kk * 4);
            LDSM_X4(af[1], aBufAddr + 16 * AST * 4 + kk * 4);
            // B: scalar loads (conflict-free quad pattern)
#pragma unroll
            for (int nt = 0; nt < 8; nt++) {
                const int c = wn + nt * 8 + gid;
                bf[nt][0] = Bs[buf][kk + tig][c];
                bf[nt][1] = Bs[buf][kk + tig + 4][c];
            }
#pragma unroll
            for (int mt = 0; mt < 2; mt++)
#pragma unroll
                for (int nt = 0; nt < 8; nt++)
                    MMA_TF32(acc[mt][nt], af[mt], bf[nt][0], bf[nt][1]);
        }

        if (t + 1 < ntiles) {
            const int nb = buf ^ 1;
            uint4 w0, w1;
            w0.x = f2tf(pa0.x); w0.y = f2tf(pa0.y); w0.z = f2tf(pa0.z); w0.w = f2tf(pa0.w);
            w1.x = f2tf(pa1.x); w1.y = f2tf(pa1.y); w1.z = f2tf(pa1.z); w1.w = f2tf(pa1.w);
            *(uint4*)&As[nb][ar][ac]     = w0;
            *(uint4*)&As[nb][ar][ac + 4] = w1;
            Bs[nb][br][bc + 0]  = f2tf(pb0.x);
            Bs[nb][br][bc + 1]  = f2tf(pb0.y);
            Bs[nb][br][bc + 2]  = f2tf(pb0.z);
            Bs[nb][br][bc + 3]  = f2tf(pb0.w);
            Bs[nb][br][bc + 64] = f2tf(pb1.x);
            Bs[nb][br][bc + 65] = f2tf(pb1.y);
            Bs[nb][br][bc + 66] = f2tf(pb1.z);
            Bs[nb][br][bc + 67] = f2tf(pb1.w);
        }
        __syncthreads();
        buf ^= 1;
    }

    // Epilogue with bias (r7)
#pragma unroll
    for (int mt = 0; mt < 2; mt++) {
        const int r0 = bm + wm + mt * 16 + gid;
#pragma unroll
        for (int nt = 0; nt < 8; nt++) {
            const int col = bn + wn + nt * 8 + 2 * tig;
            const float bx = bias[col], by = bias[col + 1];
            float2 v0 = {acc[mt][nt][0] + bx, acc[mt][nt][1] + by};
            float2 v1 = {acc[mt][nt][2] + bx, acc[mt][nt][3] + by};
            *(float2*)(C + (size_t)r0 * N + col)       = v0;
            *(float2*)(C + (size_t)(r0 + 8) * N + col) = v1;
        }
    }
}

// ---------------------------------------------------------------------------
// Tensor-core flash attention (r8, measured best): 128 queries/block,
// 4 warps x 32 queries, B-frags shared across mt, P in registers via quad shfl.
// ---------------------------------------------------------------------------
__global__ __launch_bounds__(128) void flash_attn_tc(
    const float* __restrict__ qkv, float* __restrict__ y)
{
    __shared__ uint32_t ks[64][68];
    __shared__ uint32_t vst[64][68];

    const int tid  = threadIdx.x;
    const int lane = tid & 31;
    const int wid  = tid >> 5;
    const int gid  = lane >> 2;
    const int tig  = lane & 3;
    const int wq   = wid * 32;
    const int qt0  = (int)(gridDim.x - 1 - blockIdx.x) * 128;
    const int h    = blockIdx.y;
    const int b    = blockIdx.z;

    uint32_t qf[2][8][4];
#pragma unroll
    for (int mt = 0; mt < 2; mt++) {
        const float* q0 = qkv + ((size_t)(b * SEQ + qt0 + wq + mt * 16 + gid) * (3 * DM)) + h * HD;
        const float* q1 = q0 + (size_t)8 * 3 * DM;
#pragma unroll
        for (int kk = 0; kk < 8; kk++) {
            qf[mt][kk][0] = f2tf(q0[kk * 8 + tig]     * 0.125f);
            qf[mt][kk][1] = f2tf(q1[kk * 8 + tig]     * 0.125f);
            qf[mt][kk][2] = f2tf(q0[kk * 8 + tig + 4] * 0.125f);
            qf[mt][kk][3] = f2tf(q1[kk * 8 + tig + 4] * 0.125f);
        }
    }

    float o[2][8][4];
#pragma unroll
    for (int mt = 0; mt < 2; mt++)
#pragma unroll
        for (int nt = 0; nt < 8; nt++) {
            o[mt][nt][0] = 0.f; o[mt][nt][1] = 0.f;
            o[mt][nt][2] = 0.f; o[mt][nt][3] = 0.f;
        }
    float m[2][2] = {{-1e30f, -1e30f}, {-1e30f, -1e30f}};
    float l[2][2] = {{0.f, 0.f}, {0.f, 0.f}};

    const int ntiles = qt0 / 64 + 2;
    const int krow = tid & 63;
    const int kcb  = (tid >> 6) * 32;

    const int src0 = tig >> 1;
    const int src2 = (tig >> 1) + 2;
    const bool sel = (tig & 1);

    for (int kt = 0; kt < ntiles; kt++) {
        const int kt0 = kt * 64;

        __syncthreads();
        {
            const float* kp = qkv + ((size_t)(b * SEQ + kt0 + krow) * (3 * DM)) + DM + h * HD + kcb;
            const float* vp = kp + DM;
#pragma unroll
            for (int j = 0; j < 32; j += 4) {
                float4 k4 = *(const float4*)(kp + j);
                float4 v4 = *(const float4*)(vp + j);
                uint4 w;
                w.x = f2tf(k4.x); w.y = f2tf(k4.y); w.z = f2tf(k4.z); w.w = f2tf(k4.w);
                *(uint4*)&ks[krow][kcb + j] = w;
                vst[kcb + j + 0][krow] = f2tf(v4.x);
                vst[kcb + j + 1][krow] = f2tf(v4.y);
                vst[kcb + j + 2][krow] = f2tf(v4.z);
                vst[kcb + j + 3][krow] = f2tf(v4.w);
            }
        }
        __syncthreads();

        if (kt0 > qt0 + wq + 31) continue;

        float acc[2][8][4];
#pragma unroll
        for (int mt = 0; mt < 2; mt++)
#pragma unroll
            for (int nt = 0; nt < 8; nt++) {
                acc[mt][nt][0] = 0.f; acc[mt][nt][1] = 0.f;
                acc[mt][nt][2] = 0.f; acc[mt][nt][3] = 0.f;
            }
#pragma unroll
        for (int kk = 0; kk < 8; kk++) {
            uint32_t bf0[8], bf1[8];
#pragma unroll
            for (int nt = 0; nt < 8; nt++) {
                bf0[nt] = ks[nt * 8 + gid][kk * 8 + tig];
                bf1[nt] = ks[nt * 8 + gid][kk * 8 + tig + 4];
            }
#pragma unroll
            for (int mt = 0; mt < 2; mt++)
#pragma unroll
                for (int nt = 0; nt < 8; nt++)
                    MMA_TF32(acc[mt][nt], qf[mt][kk], bf0[nt], bf1[nt]);
        }

#pragma unroll
        for (int mt = 0; mt < 2; mt++) {
            if (kt0 + 63 > qt0 + wq + mt * 16) {
                const int r0 = qt0 + wq + mt * 16 + gid, r1 = r0 + 8;
#pragma unroll
                for (int nt = 0; nt < 8; nt++) {
                    const int c = kt0 + nt * 8 + 2 * tig;
                    if (c     > r0) acc[mt][nt][0] = -1e30f;
                    if (c + 1 > r0) acc[mt][nt][1] = -1e30f;
                    if (c     > r1) acc[mt][nt][2] = -1e30f;
                    if (c + 1 > r1) acc[mt][nt][3] = -1e30f;
                }
            }
        }

#pragma unroll
        for (int mt = 0; mt < 2; mt++) {
            float mt0 = -1e30f, mt1 = -1e30f;
#pragma unroll
            for (int nt = 0; nt < 8; nt++) {
                mt0 = fmaxf(mt0, fmaxf(acc[mt][nt][0], acc[mt][nt][1]));
                mt1 = fmaxf(mt1, fmaxf(acc[mt][nt][2], acc[mt][nt][3]));
            }
            mt0 = fmaxf(mt0, __shfl_xor_sync(0xffffffffu, mt0, 1));
            mt0 = fmaxf(mt0, __shfl_xor_sync(0xffffffffu, mt0, 2));
            mt1 = fmaxf(mt1, __shfl_xor_sync(0xffffffffu, mt1, 1));
            mt1 = fmaxf(mt1, __shfl_xor_sync(0xffffffffu, mt1, 2));

            const float mn0 = fmaxf(m[mt][0], mt0), mn1 = fmaxf(m[mt][1], mt1);
            const float cr0 = __expf(m[mt][0] - mn0), cr1 = __expf(m[mt][1] - mn1);
            m[mt][0] = mn0; m[mt][1] = mn1;
            l[mt][0] *= cr0; l[mt][1] *= cr1;

            float s0 = 0.f, s1 = 0.f;
#pragma unroll
            for (int nt = 0; nt < 8; nt++) {
                const float p0 = __expf(acc[mt][nt][0] - mn0);
                const float p1 = __expf(acc[mt][nt][1] - mn0);
                const float p2 = __expf(acc[mt][nt][2] - mn1);
                const float p3 = __expf(acc[mt][nt][3] - mn1);
                s0 += p0 + p1;
                s1 += p2 + p3;
                o[mt][nt][0] *= cr0; o[mt][nt][1] *= cr0;
                o[mt][nt][2] *= cr1; o[mt][nt][3] *= cr1;
                acc[mt][nt][0] = __uint_as_float(f2tf(p0));
                acc[mt][nt][1] = __uint_as_float(f2tf(p1));
                acc[mt][nt][2] = __uint_as_float(f2tf(p2));
                acc[mt][nt][3] = __uint_as_float(f2tf(p3));
            }
            s0 += __shfl_xor_sync(0xffffffffu, s0, 1);
            s0 += __shfl_xor_sync(0xffffffffu, s0, 2);
            s1 += __shfl_xor_sync(0xffffffffu, s1, 1);
            s1 += __shfl_xor_sync(0xffffffffu, s1, 2);
            l[mt][0] += s0; l[mt][1] += s1;
        }

#pragma unroll
        for (int kk = 0; kk < 8; kk++) {
            uint32_t pa[2][4];
#pragma unroll
            for (int mt = 0; mt < 2; mt++) {
                const uint32_t e0 = __float_as_uint(acc[mt][kk][0]);
                const uint32_t e1 = __float_as_uint(acc[mt][kk][1]);
                const uint32_t e2 = __float_as_uint(acc[mt][kk][2]);
                const uint32_t e3 = __float_as_uint(acc[mt][kk][3]);
                const uint32_t u0 = __shfl_sync(0xffffffffu, e0, src0, 4);
                const uint32_t u1 = __shfl_sync(0xffffffffu, e1, src0, 4);
                pa[mt][0] = sel ? u1 : u0;
                const uint32_t v0 = __shfl_sync(0xffffffffu, e2, src0, 4);
                const uint32_t v1 = __shfl_sync(0xffffffffu, e3, src0, 4);
                pa[mt][1] = sel ? v1 : v0;
                const uint32_t w0 = __shfl_sync(0xffffffffu, e0, src2, 4);
                const uint32_t w1 = __shfl_sync(0xffffffffu, e1, src2, 4);
                pa[mt][2] = sel ? w1 : w0;
                const uint32_t x0 = __shfl_sync(0xffffffffu, e2, src2, 4);
                const uint32_t x1 = __shfl_sync(0xffffffffu, e3, src2, 4);
                pa[mt][3] = sel ? x1 : x0;
            }
#pragma unroll
            for (int nt = 0; nt < 8; nt++) {
                const uint32_t b0 = vst[nt * 8 + gid][kk * 8 + tig];
                const uint32_t b1 = vst[nt * 8 + gid][kk * 8 + tig + 4];
#pragma unroll
                for (int mt = 0; mt < 2; mt++)
                    MMA_TF32(o[mt][nt], pa[mt], b0, b1);
            }
        }
    }

#pragma unroll
    for (int mt = 0; mt < 2; mt++) {
        const float i0 = 1.f / l[mt][0], i1 = 1.f / l[mt][1];
        float* y0 = y + (size_t)(b * SEQ + qt0 + wq + mt * 16 + gid) * DM + h * HD;
        float* y1 = y0 + (size_t)8 * DM;
#pragma unroll
        for (int nt = 0; nt < 8; nt++) {
            const int c = nt * 8 + 2 * tig;
            float2 w0 = {o[mt][nt][0] * i0, o[mt][nt][1] * i0};
            float2 w1 = {o[mt][nt][2] * i1, o[mt][nt][3] * i1};
            *(float2*)(y0 + c) = w0;
            *(float2*)(y1 + c) = w1;
        }
    }
}

// ---------------------------------------------------------------------------
// Launch
// ---------------------------------------------------------------------------
extern "C" void kernel_launch(void* const* d_in, const int* in_sizes, int n_in,
                              void* d_out, int out_size)
{
    (void)in_sizes; (void)n_in; (void)out_size;
    const float* x      = (const float*)d_in[0];
    const float* w_qkv  = (const float*)d_in[1];
    const float* b_qkv  = (const float*)d_in[2];
    const float* w_proj = (const float*)d_in[3];
    const float* b_proj = (const float*)d_in[4];
    float* out = (float*)d_out;

    float* qkv = nullptr;
    float* y   = nullptr;
    cudaGetSymbolAddress((void**)&qkv, g_qkv);
    cudaGetSymbolAddress((void**)&y,   g_y);

    // 1) QKV projection: [8192,1024] @ [1024,3072] + b
    tf32_gemm_bias<<<dim3(3 * DM / 128, M_ROWS / 128), 256>>>(
        x, w_qkv, b_qkv, qkv, M_ROWS, 3 * DM, DM);

    // 2) Causal flash attention (128 queries per block, 4 warps)
    flash_attn_tc<<<dim3(SEQ / 128, NH, BATCH), 128>>>(qkv, y);

    // 3) Output projection: [8192,1024] @ [1024,1024] + b
    tf32_gemm_bias<<<dim3(DM / 128, M_ROWS / 128), 256>>>(
        y, w_proj, b_proj, out, M_ROWS, DM, DM);
}

// round 12
// speedup vs baseline: 1.2141x; 1.0087x over previous
#include <cuda_runtime.h>
#include <cuda_bf16.h>
#include <cstdint>

// Problem constants
#define BATCH 4
#define SEQ   2048
#define DM    1024
#define NH    16
#define HD    64
#define M_ROWS (BATCH*SEQ)   // 8192

// Scratch (device globals; no allocation allowed)
__device__ float g_qkv[(size_t)M_ROWS * 3 * DM];   // [B*T, 3*C] (sel, head, hd)
__device__ float g_y[(size_t)M_ROWS * DM];         // [B*T, C]

__device__ __forceinline__ uint32_t f2tf(float f) {
    uint32_t u;
    asm("cvt.rna.tf32.f32 %0, %1;" : "=r"(u) : "f"(f));
    return u;
}

__device__ __forceinline__ uint32_t smem_u32(const void* p) {
    uint32_t a;
    asm("{ .reg .u64 t; cvta.to.shared.u64 t, %1; cvt.u32.u64 %0, t; }"
        : "=r"(a) : "l"(p));
    return a;
}

#define MMA_TF32(acc, a, b0v, b1v)                                              \
    asm volatile(                                                               \
        "mma.sync.aligned.m16n8k8.row.col.f32.tf32.tf32.f32 "                   \
        "{%0,%1,%2,%3}, {%4,%5,%6,%7}, {%8,%9}, {%0,%1,%2,%3};"                 \
        : "+f"(acc[0]), "+f"(acc[1]), "+f"(acc[2]), "+f"(acc[3])                \
        : "r"(a[0]), "r"(a[1]), "r"(a[2]), "r"(a[3]), "r"(b0v), "r"(b1v))

#define LDSM_X4(r, addr)                                                        \
    asm volatile(                                                               \
        "ldmatrix.sync.aligned.m8n8.x4.shared.b16 {%0,%1,%2,%3}, [%4];"         \
        : "=r"((r)[0]), "=r"((r)[1]), "=r"((r)[2]), "=r"((r)[3])                \
        : "r"(addr))

#define TFS 136   // B smem row stride (8 mod 32 -> conflict-free quad frag loads)
#define AST 20    // A smem row stride (16B aligned; 20r mod 32 distinct over 8 rows)

// ---------------------------------------------------------------------------
// TF32 GEMM with bias: C[M,N] = A[M,K] @ B[K,N] + bias[N]
// 128x128 block tile, BK=16 double-buffered, 128 thr (4 warps 2x2),
// warp tile 64x64 (4x8 mma grid). 2 CTAs/SM (launch_bounds) so syncs of one
// CTA overlap compute of the other. A frags via ldmatrix.x4 (r10-proven
// layout), B frags scalar (proven conflict-free). tf32 cvt at store.
// Fragment traffic per CTA-ktile: A(8KB)x2 + B(8KB)x2 = 32KB (vs 48KB in r7).
// ---------------------------------------------------------------------------
__global__ __launch_bounds__(128, 2) void tf32_gemm_bias(
    const float* __restrict__ A, const float* __restrict__ B,
    const float* __restrict__ bias, float* __restrict__ C,
    int M, int N, int K)
{
    __shared__ uint32_t As[2][128][AST];   // [buf][row][k]  (10240 B per buf)
    __shared__ uint32_t Bs[2][16][TFS];    // [buf][k][col]

    const int tid  = threadIdx.x;
    const int lane = tid & 31;
    const int wid  = tid >> 5;
    const int gid  = lane >> 2;
    const int tig  = lane & 3;
    const int wm   = (wid & 1) * 64;
    const int wn   = (wid >> 1) * 64;
    const int bm   = blockIdx.y * 128;
    const int bn   = blockIdx.x * 128;

    // A staging: thread -> row tid, k 0..15 (4 x float4 -> 4 STS.128)
    // B staging: r7 pattern x2 rows: rows br, br+8; cols bc..bc+3, bc+64..bc+67
    const int br = tid >> 4;          // 0..7
    const int bc = (tid & 15) * 4;    // 0..60

    const float* Ap = A + (size_t)(bm + tid) * K;
    const float* Bp = B + (size_t)br * N + bn + bc;

    // ldmatrix base: row wm + (lane&15), k-col (lane>>4)*4
    const uint32_t aLdsm = smem_u32(&As[0][0][0]) +
        (uint32_t)(((wm + (lane & 15)) * AST + ((lane >> 4) << 2)) * 4);

    float acc[4][8][4];
#pragma unroll
    for (int mt = 0; mt < 4; mt++)
#pragma unroll
        for (int nt = 0; nt < 8; nt++)
#pragma unroll
            for (int i = 0; i < 4; i++) acc[mt][nt][i] = 0.f;

    const int ntiles = K / 16;
    float4 pa[4], pb[4];

    // Preload tile 0 -> buf 0
    {
#pragma unroll
        for (int j = 0; j < 4; j++) pa[j] = ((const float4*)Ap)[j];
        pb[0] = *(const float4*)(Bp);
        pb[1] = *(const float4*)(Bp + 64);
        pb[2] = *(const float4*)(Bp + (size_t)8 * N);
        pb[3] = *(const float4*)(Bp + (size_t)8 * N + 64);
#pragma unroll
        for (int j = 0; j < 4; j++) {
            uint4 w;
            w.x = f2tf(pa[j].x); w.y = f2tf(pa[j].y);
            w.z = f2tf(pa[j].z); w.w = f2tf(pa[j].w);
            *(uint4*)&As[0][tid][j * 4] = w;
        }
        Bs[0][br][bc + 0]      = f2tf(pb[0].x);
        Bs[0][br][bc + 1]      = f2tf(pb[0].y);
        Bs[0][br][bc + 2]      = f2tf(pb[0].z);
        Bs[0][br][bc + 3]      = f2tf(pb[0].w);
        Bs[0][br][bc + 64]     = f2tf(pb[1].x);
        Bs[0][br][bc + 65]     = f2tf(pb[1].y);
        Bs[0][br][bc + 66]     = f2tf(pb[1].z);
        Bs[0][br][bc + 67]     = f2tf(pb[1].w);
        Bs[0][br + 8][bc + 0]  = f2tf(pb[2].x);
        Bs[0][br + 8][bc + 1]  = f2tf(pb[2].y);
        Bs[0][br + 8][bc + 2]  = f2tf(pb[2].z);
        Bs[0][br + 8][bc + 3]  = f2tf(pb[2].w);
        Bs[0][br + 8][bc + 64] = f2tf(pb[3].x);
        Bs[0][br + 8][bc + 65] = f2tf(pb[3].y);
        Bs[0][br + 8][bc + 66] = f2tf(pb[3].z);
        Bs[0][br + 8][bc + 67] = f2tf(pb[3].w);
    }
    __syncthreads();

    int buf = 0;
    for (int t = 0; t < ntiles; t++) {
        if (t + 1 < ntiles) {
            const int k0 = (t + 1) * 16;
            const float* ap = Ap + k0;
            const float* bp = Bp + (size_t)k0 * N;
#pragma unroll
            for (int j = 0; j < 4; j++) pa[j] = ((const float4*)ap)[j];
            pb[0] = *(const float4*)(bp);
            pb[1] = *(const float4*)(bp + 64);
            pb[2] = *(const float4*)(bp + (size_t)8 * N);
            pb[3] = *(const float4*)(bp + (size_t)8 * N + 64);
        }

        const uint32_t aBufAddr = aLdsm + (uint32_t)(buf * 10240);
#pragma unroll
        for (int kk = 0; kk < 16; kk += 8) {
            uint32_t af[4][4], bf[8][2];
            LDSM_X4(af[0], aBufAddr + kk * 4);
            LDSM_X4(af[1], aBufAddr + 1 * 1280 + kk * 4);
            LDSM_X4(af[2], aBufAddr + 2 * 1280 + kk * 4);
            LDSM_X4(af[3], aBufAddr + 3 * 1280 + kk * 4);
#pragma unroll
            for (int nt = 0; nt < 8; nt++) {
                const int c = wn + nt * 8 + gid;
                bf[nt][0] = Bs[buf][kk + tig][c];
                bf[nt][1] = Bs[buf][kk + tig + 4][c];
            }
#pragma unroll
            for (int mt = 0; mt < 4; mt++)
#pragma unroll
                for (int nt = 0; nt < 8; nt++)
                    MMA_TF32(acc[mt][nt], af[mt], bf[nt][0], bf[nt][1]);
        }

        if (t + 1 < ntiles) {
            const int nb = buf ^ 1;
#pragma unroll
            for (int j = 0; j < 4; j++) {
                uint4 w;
                w.x = f2tf(pa[j].x); w.y = f2tf(pa[j].y);
                w.z = f2tf(pa[j].z); w.w = f2tf(pa[j].w);
                *(uint4*)&As[nb][tid][j * 4] = w;
            }
            Bs[nb][br][bc + 0]      = f2tf(pb[0].x);
            Bs[nb][br][bc + 1]      = f2tf(pb[0].y);
            Bs[nb][br][bc + 2]      = f2tf(pb[0].z);
            Bs[nb][br][bc + 3]      = f2tf(pb[0].w);
            Bs[nb][br][bc + 64]     = f2tf(pb[1].x);
            Bs[nb][br][bc + 65]     = f2tf(pb[1].y);
            Bs[nb][br][bc + 66]     = f2tf(pb[1].z);
            Bs[nb][br][bc + 67]     = f2tf(pb[1].w);
            Bs[nb][br + 8][bc + 0]  = f2tf(pb[2].x);
            Bs[nb][br + 8][bc + 1]  = f2tf(pb[2].y);
            Bs[nb][br + 8][bc + 2]  = f2tf(pb[2].z);
            Bs[nb][br + 8][bc + 3]  = f2tf(pb[2].w);
            Bs[nb][br + 8][bc + 64] = f2tf(pb[3].x);
            Bs[nb][br + 8][bc + 65] = f2tf(pb[3].y);
            Bs[nb][br + 8][bc + 66] = f2tf(pb[3].z);
            Bs[nb][br + 8][bc + 67] = f2tf(pb[3].w);
        }
        __syncthreads();
        buf ^= 1;
    }

    // Epilogue with bias
#pragma unroll
    for (int mt = 0; mt < 4; mt++) {
        const int r0 = bm + wm + mt * 16 + gid;
#pragma unroll
        for (int nt = 0; nt < 8; nt++) {
            const int col = bn + wn + nt * 8 + 2 * tig;
            const float bx = bias[col], by = bias[col + 1];
            float2 v0 = {acc[mt][nt][0] + bx, acc[mt][nt][1] + by};
            float2 v1 = {acc[mt][nt][2] + bx, acc[mt][nt][3] + by};
            *(float2*)(C + (size_t)r0 * N + col)       = v0;
            *(float2*)(C + (size_t)(r0 + 8) * N + col) = v1;
        }
    }
}

// ---------------------------------------------------------------------------
// Tensor-core flash attention (r8/r10, measured best): 128 queries/block,
// 4 warps x 32 queries, B-frags shared across mt, P in registers via quad shfl.
// ---------------------------------------------------------------------------
__global__ __launch_bounds__(128) void flash_attn_tc(
    const float* __restrict__ qkv, float* __restrict__ y)
{
    __shared__ uint32_t ks[64][68];
    __shared__ uint32_t vst[64][68];

    const int tid  = threadIdx.x;
    const int lane = tid & 31;
    const int wid  = tid >> 5;
    const int gid  = lane >> 2;
    const int tig  = lane & 3;
    const int wq   = wid * 32;
    const int qt0  = (int)(gridDim.x - 1 - blockIdx.x) * 128;
    const int h    = blockIdx.y;
    const int b    = blockIdx.z;

    uint32_t qf[2][8][4];
#pragma unroll
    for (int mt = 0; mt < 2; mt++) {
        const float* q0 = qkv + ((size_t)(b * SEQ + qt0 + wq + mt * 16 + gid) * (3 * DM)) + h * HD;
        const float* q1 = q0 + (size_t)8 * 3 * DM;
#pragma unroll
        for (int kk = 0; kk < 8; kk++) {
            qf[mt][kk][0] = f2tf(q0[kk * 8 + tig]     * 0.125f);
            qf[mt][kk][1] = f2tf(q1[kk * 8 + tig]     * 0.125f);
            qf[mt][kk][2] = f2tf(q0[kk * 8 + tig + 4] * 0.125f);
            qf[mt][kk][3] = f2tf(q1[kk * 8 + tig + 4] * 0.125f);
        }
    }

    float o[2][8][4];
#pragma unroll
    for (int mt = 0; mt < 2; mt++)
#pragma unroll
        for (int nt = 0; nt < 8; nt++) {
            o[mt][nt][0] = 0.f; o[mt][nt][1] = 0.f;
            o[mt][nt][2] = 0.f; o[mt][nt][3] = 0.f;
        }
    float m[2][2] = {{-1e30f, -1e30f}, {-1e30f, -1e30f}};
    float l[2][2] = {{0.f, 0.f}, {0.f, 0.f}};

    const int ntiles = qt0 / 64 + 2;
    const int krow = tid & 63;
    const int kcb  = (tid >> 6) * 32;

    const int src0 = tig >> 1;
    const int src2 = (tig >> 1) + 2;
    const bool sel = (tig & 1);

    for (int kt = 0; kt < ntiles; kt++) {
        const int kt0 = kt * 64;

        __syncthreads();
        {
            const float* kp = qkv + ((size_t)(b * SEQ + kt0 + krow) * (3 * DM)) + DM + h * HD + kcb;
            const float* vp = kp + DM;
#pragma unroll
            for (int j = 0; j < 32; j += 4) {
                float4 k4 = *(const float4*)(kp + j);
                float4 v4 = *(const float4*)(vp + j);
                uint4 w;
                w.x = f2tf(k4.x); w.y = f2tf(k4.y); w.z = f2tf(k4.z); w.w = f2tf(k4.w);
                *(uint4*)&ks[krow][kcb + j] = w;
                vst[kcb + j + 0][krow] = f2tf(v4.x);
                vst[kcb + j + 1][krow] = f2tf(v4.y);
                vst[kcb + j + 2][krow] = f2tf(v4.z);
                vst[kcb + j + 3][krow] = f2tf(v4.w);
            }
        }
        __syncthreads();

        if (kt0 > qt0 + wq + 31) continue;

        float acc[2][8][4];
#pragma unroll
        for (int mt = 0; mt < 2; mt++)
#pragma unroll
            for (int nt = 0; nt < 8; nt++) {
                acc[mt][nt][0] = 0.f; acc[mt][nt][1] = 0.f;
                acc[mt][nt][2] = 0.f; acc[mt][nt][3] = 0.f;
            }
#pragma unroll
        for (int kk = 0; kk < 8; kk++) {
            uint32_t bf0[8], bf1[8];
#pragma unroll
            for (int nt = 0; nt < 8; nt++) {
                bf0[nt] = ks[nt * 8 + gid][kk * 8 + tig];
                bf1[nt] = ks[nt * 8 + gid][kk * 8 + tig + 4];
            }
#pragma unroll
            for (int mt = 0; mt < 2; mt++)
#pragma unroll
                for (int nt = 0; nt < 8; nt++)
                    MMA_TF32(acc[mt][nt], qf[mt][kk], bf0[nt], bf1[nt]);
        }

#pragma unroll
        for (int mt = 0; mt < 2; mt++) {
            if (kt0 + 63 > qt0 + wq + mt * 16) {
                const int r0 = qt0 + wq + mt * 16 + gid, r1 = r0 + 8;
#pragma unroll
                for (int nt = 0; nt < 8; nt++) {
                    const int c = kt0 + nt * 8 + 2 * tig;
                    if (c     > r0) acc[mt][nt][0] = -1e30f;
                    if (c + 1 > r0) acc[mt][nt][1] = -1e30f;
                    if (c     > r1) acc[mt][nt][2] = -1e30f;
                    if (c + 1 > r1) acc[mt][nt][3] = -1e30f;
                }
            }
        }

#pragma unroll
        for (int mt = 0; mt < 2; mt++) {
            float mt0 = -1e30f, mt1 = -1e30f;
#pragma unroll
            for (int nt = 0; nt < 8; nt++) {
                mt0 = fmaxf(mt0, fmaxf(acc[mt][nt][0], acc[mt][nt][1]));
                mt1 = fmaxf(mt1, fmaxf(acc[mt][nt][2], acc[mt][nt][3]));
            }
            mt0 = fmaxf(mt0, __shfl_xor_sync(0xffffffffu, mt0, 1));
            mt0 = fmaxf(mt0, __shfl_xor_sync(0xffffffffu, mt0, 2));
            mt1 = fmaxf(mt1, __shfl_xor_sync(0xffffffffu, mt1, 1));
            mt1 = fmaxf(mt1, __shfl_xor_sync(0xffffffffu, mt1, 2));

            const float mn0 = fmaxf(m[mt][0], mt0), mn1 = fmaxf(m[mt][1], mt1);
            const float cr0 = __expf(m[mt][0] - mn0), cr1 = __expf(m[mt][1] - mn1);
            m[mt][0] = mn0; m[mt][1] = mn1;
            l[mt][0] *= cr0; l[mt][1] *= cr1;

            float s0 = 0.f, s1 = 0.f;
#pragma unroll
            for (int nt = 0; nt < 8; nt++) {
                const float p0 = __expf(acc[mt][nt][0] - mn0);
                const float p1 = __expf(acc[mt][nt][1] - mn0);
                const float p2 = __expf(acc[mt][nt][2] - mn1);
                const float p3 = __expf(acc[mt][nt][3] - mn1);
                s0 += p0 + p1;
                s1 += p2 + p3;
                o[mt][nt][0] *= cr0; o[mt][nt][1] *= cr0;
                o[mt][nt][2] *= cr1; o[mt][nt][3] *= cr1;
                acc[mt][nt][0] = __uint_as_float(f2tf(p0));
                acc[mt][nt][1] = __uint_as_float(f2tf(p1));
                acc[mt][nt][2] = __uint_as_float(f2tf(p2));
                acc[mt][nt][3] = __uint_as_float(f2tf(p3));
            }
            s0 += __shfl_xor_sync(0xffffffffu, s0, 1);
            s0 += __shfl_xor_sync(0xffffffffu, s0, 2);
            s1 += __shfl_xor_sync(0xffffffffu, s1, 1);
            s1 += __shfl_xor_sync(0xffffffffu, s1, 2);
            l[mt][0] += s0; l[mt][1] += s1;
        }

#pragma unroll
        for (int kk = 0; kk < 8; kk++) {
            uint32_t pa[2][4];
#pragma unroll
            for (int mt = 0; mt < 2; mt++) {
                const uint32_t e0 = __float_as_uint(acc[mt][kk][0]);
                const uint32_t e1 = __float_as_uint(acc[mt][kk][1]);
                const uint32_t e2 = __float_as_uint(acc[mt][kk][2]);
                const uint32_t e3 = __float_as_uint(acc[mt][kk][3]);
                const uint32_t u0 = __shfl_sync(0xffffffffu, e0, src0, 4);
                const uint32_t u1 = __shfl_sync(0xffffffffu, e1, src0, 4);
                pa[mt][0] = sel ? u1 : u0;
                const uint32_t v0 = __shfl_sync(0xffffffffu, e2, src0, 4);
                const uint32_t v1 = __shfl_sync(0xffffffffu, e3, src0, 4);
                pa[mt][1] = sel ? v1 : v0;
                const uint32_t w0 = __shfl_sync(0xffffffffu, e0, src2, 4);
                const uint32_t w1 = __shfl_sync(0xffffffffu, e1, src2, 4);
                pa[mt][2] = sel ? w1 : w0;
                const uint32_t x0 = __shfl_sync(0xffffffffu, e2, src2, 4);
                const uint32_t x1 = __shfl_sync(0xffffffffu, e3, src2, 4);
                pa[mt][3] = sel ? x1 : x0;
            }
#pragma unroll
            for (int nt = 0; nt < 8; nt++) {
                const uint32_t b0 = vst[nt * 8 + gid][kk * 8 + tig];
                const uint32_t b1 = vst[nt * 8 + gid][kk * 8 + tig + 4];
#pragma unroll
                for (int mt = 0; mt < 2; mt++)
                    MMA_TF32(o[mt][nt], pa[mt], b0, b1);
            }
        }
    }

#pragma unroll
    for (int mt = 0; mt < 2; mt++) {
        const float i0 = 1.f / l[mt][0], i1 = 1.f / l[mt][1];
        float* y0 = y + (size_t)(b * SEQ + qt0 + wq + mt * 16 + gid) * DM + h * HD;
        float* y1 = y0 + (size_t)8 * DM;
#pragma unroll
        for (int nt = 0; nt < 8; nt++) {
            const int c = nt * 8 + 2 * tig;
            float2 w0 = {o[mt][nt][0] * i0, o[mt][nt][1] * i0};
            float2 w1 = {o[mt][nt][2] * i1, o[mt][nt][3] * i1};
            *(float2*)(y0 + c) = w0;
            *(float2*)(y1 + c) = w1;
        }
    }
}

// ---------------------------------------------------------------------------
// Launch
// ---------------------------------------------------------------------------
extern "C" void kernel_launch(void* const* d_in, const int* in_sizes, int n_in,
                              void* d_out, int out_size)
{
    (void)in_sizes; (void)n_in; (void)out_size;
    const float* x      = (const float*)d_in[0];
    const float* w_qkv  = (const float*)d_in[1];
    const float* b_qkv  = (const float*)d_in[2];
    const float* w_proj = (const float*)d_in[3];
    const float* b_proj = (const float*)d_in[4];
    float* out = (float*)d_out;

    float* qkv = nullptr;
    float* y   = nullptr;
    cudaGetSymbolAddress((void**)&qkv, g_qkv);
    cudaGetSymbolAddress((void**)&y,   g_y);

    // 1) QKV projection: [8192,1024] @ [1024,3072] + b
    tf32_gemm_bias<<<dim3(3 * DM / 128, M_ROWS / 128), 128>>>(
        x, w_qkv, b_qkv, qkv, M_ROWS, 3 * DM, DM);

    // 2) Causal flash attention (128 queries per block, 4 warps)
    flash_attn_tc<<<dim3(SEQ / 128, NH, BATCH), 128>>>(qkv, y);

    // 3) Output projection: [8192,1024] @ [1024,1024] + b
    tf32_gemm_bias<<<dim3(DM / 128, M_ROWS / 128), 128>>>(
        y, w_proj, b_proj, out, M_ROWS, DM, DM);
}